// round 9
// baseline (speedup 1.0000x reference)
#include <cuda_runtime.h>
#include <cuda_bf16.h>
#include <cstdint>
#include <math.h>

#define SEQ 4096
#define DM  1024
#define NH  16
#define DK  64

using bf16 = __nv_bfloat16;

// ---------------------------------------------------------------------------
// Scratch (__device__ globals: allocation-guard safe) — all bf16 hi/lo pairs
// ---------------------------------------------------------------------------
__device__ bf16 g_xqh[SEQ * DM], g_xql[SEQ * DM];
__device__ bf16 g_xkh[SEQ * DM], g_xkl[SEQ * DM];
__device__ bf16 g_xvh[SEQ * DM], g_xvl[SEQ * DM];
__device__ bf16 g_wqh[DM * DM],  g_wql[DM * DM];
__device__ bf16 g_wkh[DM * DM],  g_wkl[DM * DM];
__device__ bf16 g_wvh[DM * DM],  g_wvl[DM * DM];
__device__ bf16 g_woh[DM * DM],  g_wol[DM * DM];
__device__ bf16 g_Qh[SEQ * DM],  g_Ql[SEQ * DM];
__device__ bf16 g_Kh[SEQ * DM],  g_Kl[SEQ * DM];
__device__ bf16 g_Vh[SEQ * DM],  g_Vl[SEQ * DM];
__device__ bf16 g_oh[SEQ * DM],  g_ol[SEQ * DM];

// ---------------------------------------------------------------------------
// PTX helpers — valid at compute_103 (no tcgen05)
// ---------------------------------------------------------------------------
__device__ __forceinline__ uint32_t smem_u32(const void* p) {
    uint32_t a;
    asm("{ .reg .u64 t; cvta.to.shared.u64 t, %1; cvt.u32.u64 %0, t; }" : "=r"(a) : "l"(p));
    return a;
}
__device__ __forceinline__ void ldsm_x4(uint32_t* r, uint32_t addr) {
    asm volatile("ldmatrix.sync.aligned.m8n8.x4.shared.b16 {%0,%1,%2,%3}, [%4];"
                 : "=r"(r[0]), "=r"(r[1]), "=r"(r[2]), "=r"(r[3]) : "r"(addr));
}
__device__ __forceinline__ void ldsm_x2(uint32_t* r, uint32_t addr) {
    asm volatile("ldmatrix.sync.aligned.m8n8.x2.shared.b16 {%0,%1}, [%2];"
                 : "=r"(r[0]), "=r"(r[1]) : "r"(addr));
}
__device__ __forceinline__ void ldsm_x2_trans(uint32_t* r, uint32_t addr) {
    asm volatile("ldmatrix.sync.aligned.m8n8.x2.trans.shared.b16 {%0,%1}, [%2];"
                 : "=r"(r[0]), "=r"(r[1]) : "r"(addr));
}
__device__ __forceinline__ void mma_bf16(float* c, const uint32_t* a, const uint32_t* b) {
    asm volatile(
        "mma.sync.aligned.m16n8k16.row.col.f32.bf16.bf16.f32 "
        "{%0,%1,%2,%3}, {%4,%5,%6,%7}, {%8,%9}, {%0,%1,%2,%3};"
        : "+f"(c[0]), "+f"(c[1]), "+f"(c[2]), "+f"(c[3])
        : "r"(a[0]), "r"(a[1]), "r"(a[2]), "r"(a[3]), "r"(b[0]), "r"(b[1]));
}
__device__ __forceinline__ void cp16(uint32_t s, const void* g) {
    asm volatile("cp.async.cg.shared.global [%0], [%1], 16;" :: "r"(s), "l"(g));
}
#define CP_COMMIT() asm volatile("cp.async.commit_group;" ::: "memory")
#define CP_WAIT(n)  asm volatile("cp.async.wait_group %0;" :: "n"(n) : "memory")

__device__ __forceinline__ void split_pack2(float x, float y, uint32_t& hi, uint32_t& lo) {
    __nv_bfloat162 h2 = __floats2bfloat162_rn(x, y);
    float rx = x - __bfloat162float(h2.x);
    float ry = y - __bfloat162float(h2.y);
    __nv_bfloat162 l2 = __floats2bfloat162_rn(rx, ry);
    hi = *reinterpret_cast<uint32_t*>(&h2);
    lo = *reinterpret_cast<uint32_t*>(&l2);
}

// ---------------------------------------------------------------------------
// Fused fp32 -> bf16 hi/lo split: up to 4 tensors in one launch (blockIdx.y)
// ---------------------------------------------------------------------------
struct SplitArgs {
    const float* x[4];
    bf16* h[4];
    bf16* l[4];
};

__global__ __launch_bounds__(256) void split_multi(SplitArgs a, int n)
{
    int z = blockIdx.y;
    const float* x = a.x[z];
    bf16 *h = a.h[z], *l = a.l[z];
    int i = (blockIdx.x * 256 + threadIdx.x) * 4;
    if (i >= n) return;
    float4 v = *reinterpret_cast<const float4*>(x + i);
    uint32_t h01, l01, h23, l23;
    split_pack2(v.x, v.y, h01, l01);
    split_pack2(v.z, v.w, h23, l23);
    *reinterpret_cast<uint32_t*>(h + i)     = h01;
    *reinterpret_cast<uint32_t*>(h + i + 2) = h23;
    *reinterpret_cast<uint32_t*>(l + i)     = l01;
    *reinterpret_cast<uint32_t*>(l + i + 2) = l23;
}

// ---------------------------------------------------------------------------
// HMMA GEMM body: Y = A @ B^T, 3xBF16 split, cp.async double-buffered.
// CTA 128x128 (8 warps 64x32), BK=32, pitch GLD=40 bf16.
// ---------------------------------------------------------------------------
#define GLD 40
#define GSTAGE_B 40960   // 4 tiles * 128 * GLD * 2 bytes

template<bool SPLIT_OUT>
__device__ __forceinline__ void gemm_body(
    const bf16* __restrict__ Ah, const bf16* __restrict__ Al,
    const bf16* __restrict__ Bh, const bf16* __restrict__ Bl,
    float* __restrict__ Yf, bf16* __restrict__ Yh, bf16* __restrict__ Yl,
    bf16* smg)
{
    const int tid  = threadIdx.x;
    const int lane = tid & 31;
    const int wid  = tid >> 5;
    const int wm   = wid >> 2;
    const int wn   = wid & 3;
    const int bm   = blockIdx.y, bn = blockIdx.x;
    const uint32_t uS = smem_u32(smg);

    auto issue = [&](int ktile) {
        const int kt = ktile * 32;
        const uint32_t sbase = uS + (ktile & 1) * GSTAGE_B;
#pragma unroll
        for (int it = 0; it < 8; it++) {
            int idx  = tid + it * 256;
            int tile = idx >> 9;
            int rem  = idx & 511;
            int r    = rem >> 2, j = rem & 3;
            const bf16* gp = (tile == 0 ? Ah : tile == 1 ? Al : tile == 2 ? Bh : Bl);
            int row = ((tile < 2) ? bm : bn) * 128 + r;
            cp16(sbase + tile * 10240 + r * 80 + j * 16,
                 gp + (size_t)row * DM + kt + j * 8);
        }
    };

    float acc[4][4][4];
#pragma unroll
    for (int i = 0; i < 4; i++)
#pragma unroll
        for (int j = 0; j < 4; j++)
#pragma unroll
            for (int k = 0; k < 4; k++) acc[i][j][k] = 0.f;

    const int a_r = (lane & 15), a_c = (lane >> 4) * 8;
    const int b_r = (lane & 7),  b_c = ((lane >> 3) & 1) * 8;

    issue(0);
    CP_COMMIT();

    for (int kt = 0; kt < 32; kt++) {
        if (kt + 1 < 32) { issue(kt + 1); CP_COMMIT(); CP_WAIT(1); }
        else             { CP_WAIT(0); }
        __syncthreads();

        const uint32_t st = uS + (kt & 1) * GSTAGE_B;
        const uint32_t uAh = st, uAl = st + 10240, uBh = st + 20480, uBl = st + 30720;

#pragma unroll
        for (int s = 0; s < 2; s++) {
            uint32_t ah[4][4], al[4][4], bh[4][2], bl[4][2];
#pragma unroll
            for (int i = 0; i < 4; i++) {
                uint32_t off = (uint32_t)(((wm * 64 + i * 16 + a_r) * GLD + s * 16 + a_c) * 2);
                ldsm_x4(ah[i], uAh + off);
                ldsm_x4(al[i], uAl + off);
            }
#pragma unroll
            for (int j = 0; j < 4; j++) {
                uint32_t off = (uint32_t)(((wn * 32 + j * 8 + b_r) * GLD + s * 16 + b_c) * 2);
                ldsm_x2(bh[j], uBh + off);
                ldsm_x2(bl[j], uBl + off);
            }
#pragma unroll
            for (int i = 0; i < 4; i++)
#pragma unroll
                for (int j = 0; j < 4; j++) {
                    mma_bf16(acc[i][j], ah[i], bh[j]);
                    mma_bf16(acc[i][j], ah[i], bl[j]);
                    mma_bf16(acc[i][j], al[i], bh[j]);
                }
        }
        __syncthreads();
    }

    const int g = lane >> 2, t = lane & 3;
#pragma unroll
    for (int i = 0; i < 4; i++) {
        int row0 = bm * 128 + wm * 64 + i * 16 + g;
#pragma unroll
        for (int j = 0; j < 4; j++) {
            int col = bn * 128 + wn * 32 + j * 8 + 2 * t;
            if (SPLIT_OUT) {
                uint32_t hi, lo;
                split_pack2(acc[i][j][0], acc[i][j][1], hi, lo);
                *reinterpret_cast<uint32_t*>(Yh + (size_t)row0 * DM + col) = hi;
                *reinterpret_cast<uint32_t*>(Yl + (size_t)row0 * DM + col) = lo;
                split_pack2(acc[i][j][2], acc[i][j][3], hi, lo);
                *reinterpret_cast<uint32_t*>(Yh + (size_t)(row0 + 8) * DM + col) = hi;
                *reinterpret_cast<uint32_t*>(Yl + (size_t)(row0 + 8) * DM + col) = lo;
            } else {
                *reinterpret_cast<float2*>(Yf + (size_t)row0 * DM + col) =
                    make_float2(acc[i][j][0], acc[i][j][1]);
                *reinterpret_cast<float2*>(Yf + (size_t)(row0 + 8) * DM + col) =
                    make_float2(acc[i][j][2], acc[i][j][3]);
            }
        }
    }
}

// Fused Q/K/V projection: blockIdx.z selects the (input, weight, output) set.
struct QKVArgs {
    const bf16 *Ah[3], *Al[3], *Bh[3], *Bl[3];
    bf16 *Yh[3], *Yl[3];
};

__global__ __launch_bounds__(256) void gemm_qkv(QKVArgs a)
{
    extern __shared__ __align__(16) bf16 smg[];
    int z = blockIdx.z;
    gemm_body<true>(a.Ah[z], a.Al[z], a.Bh[z], a.Bl[z], nullptr, a.Yh[z], a.Yl[z], smg);
}

__global__ __launch_bounds__(256) void gemm_out(
    const bf16* __restrict__ Ah, const bf16* __restrict__ Al,
    const bf16* __restrict__ Bh, const bf16* __restrict__ Bl,
    float* __restrict__ Yf)
{
    extern __shared__ __align__(16) bf16 smg[];
    gemm_body<false>(Ah, Al, Bh, Bl, Yf, nullptr, nullptr, smg);
}

// ---------------------------------------------------------------------------
// HMMA flash attention. Q fragments held in REGISTERS (loaded once via
// ldmatrix from stage-0 smem), so smem = 2 KV stages only -> 2 CTAs/SM.
// CTA = (head, 128 Q rows); 8 warps x (16 rows x 64 cols); Bc = 64.
// ---------------------------------------------------------------------------
#define FP 72            // pitch bf16 (144 B)
#define KV_STAGE 36864   // 4 arrays * 64 * FP * 2 B

__global__ __launch_bounds__(256, 2) void flash_mma(
    const bf16* __restrict__ Qh, const bf16* __restrict__ Ql,
    const bf16* __restrict__ Kh, const bf16* __restrict__ Kl,
    const bf16* __restrict__ Vh, const bf16* __restrict__ Vl,
    bf16* __restrict__ Oh, bf16* __restrict__ Ol)
{
    extern __shared__ __align__(16) bf16 sb[];
    const int tid  = threadIdx.x;
    const int lane = tid & 31;
    const int wid  = tid >> 5;
    const int g    = lane >> 2;
    const int t    = lane & 3;
    const int h    = blockIdx.x;
    const int qb   = blockIdx.y;
    const uint32_t uS = smem_u32(sb);

    const int a_r = (lane & 15), a_c = (lane >> 4) * 8;
    const int b_r = (lane & 7),  b_c = ((lane >> 3) & 1) * 8;
    const int v_r = (lane & 15);

    // ---- stage Q into buffer 0, then ldmatrix into registers ----
#pragma unroll
    for (int it = 0; it < 8; it++) {
        int idx = tid + it * 256;               // 0..2047
        int arr = idx >> 10;                    // 0: Qh, 1: Ql
        int rem = idx & 1023;
        int r   = rem >> 3, j = rem & 7;
        const bf16* gp = arr ? Ql : Qh;
        cp16(uS + arr * 18432 + r * 144 + j * 16,
             gp + (size_t)(qb * 128 + r) * DM + h * DK + j * 8);
    }
    CP_COMMIT(); CP_WAIT(0);
    __syncthreads();

    uint32_t qfh[4][4], qfl[4][4];
#pragma unroll
    for (int kc = 0; kc < 4; kc++) {
        uint32_t aoff = (uint32_t)(((wid * 16 + a_r) * FP + kc * 16 + a_c) * 2);
        ldsm_x4(qfh[kc], uS + aoff);
        ldsm_x4(qfl[kc], uS + 18432 + aoff);
    }
    __syncthreads();   // all warps done reading Q before KV overwrites buffer 0

    auto issue_kv = [&](int kv) {
        const uint32_t base = uS + (kv & 1) * KV_STAGE;
#pragma unroll
        for (int it = 0; it < 8; it++) {
            int idx = tid + it * 256;
            int arr = idx >> 9;                 // Kh,Kl,Vh,Vl
            int rem = idx & 511;
            int r   = rem >> 3, j = rem & 7;
            const bf16* gp = (arr == 0 ? Kh : arr == 1 ? Kl : arr == 2 ? Vh : Vl);
            cp16(base + arr * 9216 + r * 144 + j * 16,
                 gp + (size_t)(kv * 64 + r) * DM + h * DK + j * 8);
        }
    };

    issue_kv(0);
    CP_COMMIT();

    float o[8][4];
#pragma unroll
    for (int nf = 0; nf < 8; nf++)
#pragma unroll
        for (int k = 0; k < 4; k++) o[nf][k] = 0.f;
    float m0 = -1e30f, m1 = -1e30f, l0 = 0.f, l1 = 0.f;

    for (int kv = 0; kv < SEQ / 64; kv++) {
        if (kv + 1 < SEQ / 64) { issue_kv(kv + 1); CP_COMMIT(); CP_WAIT(1); }
        else                   { CP_WAIT(0); }
        __syncthreads();

        const uint32_t kb  = uS + (kv & 1) * KV_STAGE;
        const uint32_t uKh = kb, uKl = kb + 9216, uVh = kb + 18432, uVl = kb + 27648;

        // ---- S = Q @ K^T (3xBF16), Q from registers ----
        float s[8][4];
#pragma unroll
        for (int nf = 0; nf < 8; nf++)
#pragma unroll
            for (int k = 0; k < 4; k++) s[nf][k] = 0.f;

#pragma unroll
        for (int kc = 0; kc < 4; kc++) {
#pragma unroll
            for (int nf = 0; nf < 8; nf++) {
                uint32_t bh[2], bl[2];
                uint32_t boff = (uint32_t)(((nf * 8 + b_r) * FP + kc * 16 + b_c) * 2);
                ldsm_x2(bh, uKh + boff);
                ldsm_x2(bl, uKl + boff);
                mma_bf16(s[nf], qfh[kc], bh);
                mma_bf16(s[nf], qfh[kc], bl);
                mma_bf16(s[nf], qfl[kc], bh);
            }
        }

        // ---- scale + online softmax ----
        float mx0 = -1e30f, mx1 = -1e30f;
#pragma unroll
        for (int nf = 0; nf < 8; nf++) {
            s[nf][0] *= 0.125f; s[nf][1] *= 0.125f;
            s[nf][2] *= 0.125f; s[nf][3] *= 0.125f;
            mx0 = fmaxf(mx0, fmaxf(s[nf][0], s[nf][1]));
            mx1 = fmaxf(mx1, fmaxf(s[nf][2], s[nf][3]));
        }
        mx0 = fmaxf(mx0, __shfl_xor_sync(0xffffffffu, mx0, 1));
        mx0 = fmaxf(mx0, __shfl_xor_sync(0xffffffffu, mx0, 2));
        mx1 = fmaxf(mx1, __shfl_xor_sync(0xffffffffu, mx1, 1));
        mx1 = fmaxf(mx1, __shfl_xor_sync(0xffffffffu, mx1, 2));

        float mn0 = fmaxf(m0, mx0), mn1 = fmaxf(m1, mx1);
        float c0 = __expf(m0 - mn0), c1 = __expf(m1 - mn1);
        float rs0 = 0.f, rs1 = 0.f;
#pragma unroll
        for (int nf = 0; nf < 8; nf++) {
            s[nf][0] = __expf(s[nf][0] - mn0);
            s[nf][1] = __expf(s[nf][1] - mn0);
            s[nf][2] = __expf(s[nf][2] - mn1);
            s[nf][3] = __expf(s[nf][3] - mn1);
            rs0 += s[nf][0] + s[nf][1];
            rs1 += s[nf][2] + s[nf][3];
        }
        rs0 += __shfl_xor_sync(0xffffffffu, rs0, 1);
        rs0 += __shfl_xor_sync(0xffffffffu, rs0, 2);
        rs1 += __shfl_xor_sync(0xffffffffu, rs1, 1);
        rs1 += __shfl_xor_sync(0xffffffffu, rs1, 2);
        l0 = l0 * c0 + rs0;
        l1 = l1 * c1 + rs1;
        m0 = mn0; m1 = mn1;
#pragma unroll
        for (int nf = 0; nf < 8; nf++) {
            o[nf][0] *= c0; o[nf][1] *= c0;
            o[nf][2] *= c1; o[nf][3] *= c1;
        }

        // ---- O += P @ V (3xBF16); V via ldmatrix.trans ----
#pragma unroll
        for (int kc = 0; kc < 4; kc++) {
            uint32_t pah[4], pal[4];
            split_pack2(s[2 * kc][0],     s[2 * kc][1],     pah[0], pal[0]);
            split_pack2(s[2 * kc][2],     s[2 * kc][3],     pah[1], pal[1]);
            split_pack2(s[2 * kc + 1][0], s[2 * kc + 1][1], pah[2], pal[2]);
            split_pack2(s[2 * kc + 1][2], s[2 * kc + 1][3], pah[3], pal[3]);
#pragma unroll
            for (int nf = 0; nf < 8; nf++) {
                uint32_t vbh[2], vbl[2];
                uint32_t voff = (uint32_t)(((kc * 16 + v_r) * FP + nf * 8) * 2);
                ldsm_x2_trans(vbh, uVh + voff);
                ldsm_x2_trans(vbl, uVl + voff);
                mma_bf16(o[nf], pah, vbh);
                mma_bf16(o[nf], pah, vbl);
                mma_bf16(o[nf], pal, vbh);
            }
        }
        __syncthreads();
    }

    // ---- normalize + store as bf16 hi/lo ----
    float i0 = 1.f / l0, i1 = 1.f / l1;
    int row0 = qb * 128 + wid * 16 + g;
#pragma unroll
    for (int nf = 0; nf < 8; nf++) {
        int col = h * DK + nf * 8 + 2 * t;
        uint32_t hi, lo;
        split_pack2(o[nf][0] * i0, o[nf][1] * i0, hi, lo);
        *reinterpret_cast<uint32_t*>(Oh + (size_t)row0 * DM + col) = hi;
        *reinterpret_cast<uint32_t*>(Ol + (size_t)row0 * DM + col) = lo;
        split_pack2(o[nf][2] * i1, o[nf][3] * i1, hi, lo);
        *reinterpret_cast<uint32_t*>(Oh + (size_t)(row0 + 8) * DM + col) = hi;
        *reinterpret_cast<uint32_t*>(Ol + (size_t)(row0 + 8) * DM + col) = lo;
    }
}

// ---------------------------------------------------------------------------
extern "C" void kernel_launch(void* const* d_in, const int* in_sizes, int n_in,
                              void* d_out, int out_size)
{
    const float* query = (const float*)d_in[0];
    const float* key_t = (const float*)d_in[1];
    const float* value = (const float*)d_in[2];
    const float* w_q   = (const float*)d_in[3];
    const float* w_k   = (const float*)d_in[4];
    const float* w_v   = (const float*)d_in[5];
    const float* w_o   = (const float*)d_in[6];
    float* out = (float*)d_out;

    bf16 *xqh, *xql, *xkh, *xkl, *xvh, *xvl;
    bf16 *wqh, *wql, *wkh, *wkl, *wvh, *wvl, *woh, *wol;
    bf16 *Qh, *Ql, *Kh, *Kl, *Vh, *Vl, *oh, *ol;
    cudaGetSymbolAddress((void**)&xqh, g_xqh); cudaGetSymbolAddress((void**)&xql, g_xql);
    cudaGetSymbolAddress((void**)&xkh, g_xkh); cudaGetSymbolAddress((void**)&xkl, g_xkl);
    cudaGetSymbolAddress((void**)&xvh, g_xvh); cudaGetSymbolAddress((void**)&xvl, g_xvl);
    cudaGetSymbolAddress((void**)&wqh, g_wqh); cudaGetSymbolAddress((void**)&wql, g_wql);
    cudaGetSymbolAddress((void**)&wkh, g_wkh); cudaGetSymbolAddress((void**)&wkl, g_wkl);
    cudaGetSymbolAddress((void**)&wvh, g_wvh); cudaGetSymbolAddress((void**)&wvl, g_wvl);
    cudaGetSymbolAddress((void**)&woh, g_woh); cudaGetSymbolAddress((void**)&wol, g_wol);
    cudaGetSymbolAddress((void**)&Qh,  g_Qh);  cudaGetSymbolAddress((void**)&Ql,  g_Ql);
    cudaGetSymbolAddress((void**)&Kh,  g_Kh);  cudaGetSymbolAddress((void**)&Kl,  g_Kl);
    cudaGetSymbolAddress((void**)&Vh,  g_Vh);  cudaGetSymbolAddress((void**)&Vl,  g_Vl);
    cudaGetSymbolAddress((void**)&oh,  g_oh);  cudaGetSymbolAddress((void**)&ol,  g_ol);

    const int smem_gemm = 2 * GSTAGE_B;     // 81920 B
    const int smem_attn = 2 * KV_STAGE;     // 73728 B
    cudaFuncSetAttribute(gemm_qkv,  cudaFuncAttributeMaxDynamicSharedMemorySize, smem_gemm);
    cudaFuncSetAttribute(gemm_out,  cudaFuncAttributeMaxDynamicSharedMemorySize, smem_gemm);
    cudaFuncSetAttribute(flash_mma, cudaFuncAttributeMaxDynamicSharedMemorySize, smem_attn);

    const int nAct = SEQ * DM, nW = DM * DM;

    // one launch for the 3 activation splits, one for the 4 weight splits
    SplitArgs sa{};
    sa.x[0] = query; sa.h[0] = xqh; sa.l[0] = xql;
    sa.x[1] = key_t; sa.h[1] = xkh; sa.l[1] = xkl;
    sa.x[2] = value; sa.h[2] = xvh; sa.l[2] = xvl;
    split_multi<<<dim3(nAct / 1024, 3), 256>>>(sa, nAct);

    SplitArgs sw{};
    sw.x[0] = w_q; sw.h[0] = wqh; sw.l[0] = wql;
    sw.x[1] = w_k; sw.h[1] = wkh; sw.l[1] = wkl;
    sw.x[2] = w_v; sw.h[2] = wvh; sw.l[2] = wvl;
    sw.x[3] = w_o; sw.h[3] = woh; sw.l[3] = wol;
    split_multi<<<dim3(nW / 1024, 4), 256>>>(sw, nW);

    // fused Q/K/V projections (one launch, grid.z = 3)
    QKVArgs qa{};
    qa.Ah[0] = xqh; qa.Al[0] = xql; qa.Bh[0] = wqh; qa.Bl[0] = wql; qa.Yh[0] = Qh; qa.Yl[0] = Ql;
    qa.Ah[1] = xkh; qa.Al[1] = xkl; qa.Bh[1] = wkh; qa.Bl[1] = wkl; qa.Yh[1] = Kh; qa.Yl[1] = Kl;
    qa.Ah[2] = xvh; qa.Al[2] = xvl; qa.Bh[2] = wvh; qa.Bl[2] = wvl; qa.Yh[2] = Vh; qa.Yl[2] = Vl;
    gemm_qkv<<<dim3(DM / 128, SEQ / 128, 3), 256, smem_gemm>>>(qa);

    dim3 agrid(NH, SEQ / 128);   // (16, 32)
    flash_mma<<<agrid, 256, smem_attn>>>(Qh, Ql, Kh, Kl, Vh, Vl, oh, ol);

    gemm_out<<<dim3(DM / 128, SEQ / 128), 256, smem_gemm>>>(oh, ol, woh, wol, out);
}